// round 8
// baseline (speedup 1.0000x reference)
#include <cuda_runtime.h>
#include <cstdint>

namespace {

constexpr int kB = 16, kC = 64, kH = 128, kW = 128;
constexpr int PX = 68;    // Q/K w-major pitch; 68 % 32 == 4
constexpr int PV = 132;   // V c-major pitch; 132 % 32 == 4
constexpr int NTHR = 512;
constexpr int PLANE = kH * kW;

// smem layout (float offsets)
constexpr int OFF_XA   = 0;      // [64][128] swizzled c-major x_l: word c*128 + (w ^ 8*(c&3))
constexpr int OFF_XB   = 8192;
constexpr int OFF_QB   = 16384;  // Q w-major [128][68] -> V1 c-major [64][132]
constexpr int OFF_KB   = 25088;  // K -> V2
constexpr int OFF_E    = 33792;  // [128][128] swizzled: r*128 + (c ^ (8*(r&3)|4*((r>>2)&1)))
constexpr int OFF_WB1  = 50176;  // bf16 packed weights: 64 rows * 36 words
constexpr int OFF_WB2  = 52480;
constexpr int OFF_ROWP = 54784;  // [4][128]
constexpr int OFF_COLP = 55296;  // [4][128]
constexpr int OFF_MEANL= 55808;  // meanl,rstdl,meanh,rstdh 128 each
constexpr int OFF_T    = 56320;  // t1q,t2q,t1k,t2k 64 each
constexpr int OFF_INV  = 56576;  // invrow 128, invcol 128
constexpr int SMEM_FLOATS = 56832;  // 227,328 B

__device__ __forceinline__ uint32_t f2t(float x) {
  uint32_t r;
  asm("cvt.rna.tf32.f32 %0, %1;" : "=r"(r) : "f"(x));
  return r;
}
__device__ __forceinline__ float tround(float x) {
  return __uint_as_float(f2t(x));
}
__device__ __forceinline__ uint32_t fu(float x) { return __float_as_uint(x); }

__device__ __forceinline__ void mma8(float* c, uint32_t a0, uint32_t a1, uint32_t a2,
                                     uint32_t a3, uint32_t b0, uint32_t b1) {
  asm volatile(
      "mma.sync.aligned.m16n8k8.row.col.f32.tf32.tf32.f32 "
      "{%0,%1,%2,%3},{%4,%5,%6,%7},{%8,%9},{%0,%1,%2,%3};"
      : "+f"(c[0]), "+f"(c[1]), "+f"(c[2]), "+f"(c[3])
      : "r"(a0), "r"(a1), "r"(a2), "r"(a3), "r"(b0), "r"(b1));
}

// round-to-nearest-even fp32 -> bf16 bits
__device__ __forceinline__ uint16_t f2bf(float x) {
  const uint32_t b = fu(x);
  return (uint16_t)((b + 0x7FFFu + ((b >> 16) & 1u)) >> 16);
}
__device__ __forceinline__ float bf2f(uint16_t h) {
  return __uint_as_float(((uint32_t)h) << 16);
}
// packed index within 8-col group: k -> (k&56) | ((k&3)<<1) | ((k>>2)&1)
__device__ __forceinline__ int wperm(int c) {
  return (c & 56) | ((c & 3) << 1) | ((c >> 2) & 1);
}

// Stage 64x64 weight as bf16 packed, fold LN gamma; t1[j]=sum wf, t2[j]=sum raw*b.
// 256 threads (one warp half), local t in [0,256).
__device__ __forceinline__ void stage_fold(
    const float* __restrict__ Wsrc, const float* __restrict__ g,
    const float* __restrict__ bb, uint16_t* __restrict__ WBh,
    float* __restrict__ t1, float* __restrict__ t2, int t) {
  const int j = t >> 2;
  const int c0 = (t & 3) * 16;
  float s1 = 0.f, s2 = 0.f;
#pragma unroll
  for (int u = 0; u < 16; u++) {
    const int c = c0 + u;
    const float raw = Wsrc[j * 64 + c];
    const uint16_t hb = f2bf(raw * g[c]);
    WBh[j * 72 + wperm(c)] = hb;
    s1 += bf2f(hb);
    s2 += raw * bb[c];
  }
  s1 += __shfl_xor_sync(0xffffffffu, s1, 1);
  s1 += __shfl_xor_sync(0xffffffffu, s1, 2);
  s2 += __shfl_xor_sync(0xffffffffu, s2, 1);
  s2 += __shfl_xor_sync(0xffffffffu, s2, 2);
  if ((t & 3) == 0) { t1[j] = s1; t2[j] = s2; }
}

__device__ __forceinline__ void stage_raw(
    const float* __restrict__ Wsrc, uint16_t* __restrict__ WBh, int t) {
  const int j = t >> 2;
  const int c0 = (t & 3) * 16;
#pragma unroll
  for (int u = 0; u < 16; u++) {
    const int c = c0 + u;
    WBh[j * 72 + wperm(c)] = f2bf(Wsrc[j * 64 + c]);
  }
}

// C[128][64] = A @ W^T. A = swizzled c-major x [64][128]; W = bf16-packed.
// 8 warps (w8 in [0,8)), grid 4(m)x2(n), 32x32 tiles.
// MODE 0: LN epilogue -> w-major [w][PX]. MODE 1: raw -> c-major [c][PV].
template <int MODE>
__device__ __forceinline__ void gemm_xw(
    const float* __restrict__ A, const uint32_t* __restrict__ WBw,
    float* __restrict__ C, int w8, int qr, int qc,
    const float* __restrict__ mean, const float* __restrict__ rstd,
    const float* __restrict__ t1, const float* __restrict__ t2) {
  const int r0 = (w8 & 3) * 32;
  const int c0 = (w8 >> 2) * 32;
  const int sA = qc << 3;
  float acc[2][4][4];
#pragma unroll
  for (int mi = 0; mi < 2; mi++)
#pragma unroll
    for (int nj = 0; nj < 4; nj++)
#pragma unroll
      for (int e = 0; e < 4; e++) acc[mi][nj][e] = 0.f;

#pragma unroll
  for (int k0 = 0; k0 < 64; k0 += 8) {
    const float* a0 = A + (k0 + qc) * 128;
    const float* a4 = A + (k0 + qc + 4) * 128;
    uint32_t af[2][4];
#pragma unroll
    for (int mi = 0; mi < 2; mi++) {
      const int w = r0 + mi * 16 + qr;
      af[mi][0] = f2t(a0[w ^ sA]);
      af[mi][1] = f2t(a0[(w + 8) ^ sA]);
      af[mi][2] = f2t(a4[w ^ sA]);
      af[mi][3] = f2t(a4[(w + 8) ^ sA]);
    }
    uint32_t bf[4][2];
#pragma unroll
    for (int nj = 0; nj < 4; nj++) {
      const uint32_t v = WBw[(c0 + nj * 8 + qr) * 36 + (k0 >> 1) + qc];
      bf[nj][0] = v << 16;
      bf[nj][1] = v & 0xffff0000u;
    }
#pragma unroll
    for (int mi = 0; mi < 2; mi++)
#pragma unroll
      for (int nj = 0; nj < 4; nj++)
        mma8(acc[mi][nj], af[mi][0], af[mi][1], af[mi][2], af[mi][3], bf[nj][0], bf[nj][1]);
  }

#pragma unroll
  for (int mi = 0; mi < 2; mi++) {
    const int ra = r0 + mi * 16 + qr;
#pragma unroll
    for (int nj = 0; nj < 4; nj++) {
      const int cc = c0 + nj * 8 + 2 * qc;
      float v0 = acc[mi][nj][0], v1 = acc[mi][nj][1];
      float v2 = acc[mi][nj][2], v3 = acc[mi][nj][3];
      if (MODE == 0) {
        const float m0 = mean[ra], rs0 = rstd[ra];
        const float m1 = mean[ra + 8], rs1 = rstd[ra + 8];
        const float ta = t1[cc], tb = t1[cc + 1];
        const float ua = t2[cc], ub = t2[cc + 1];
        v0 = rs0 * (v0 - m0 * ta) + ua;
        v1 = rs0 * (v1 - m0 * tb) + ub;
        v2 = rs1 * (v2 - m1 * ta) + ua;
        v3 = rs1 * (v3 - m1 * tb) + ub;
        *(float2*)&C[ra * PX + cc] = make_float2(tround(v0), tround(v1));
        *(float2*)&C[(ra + 8) * PX + cc] = make_float2(tround(v2), tround(v3));
      } else {
        C[cc * PV + ra] = tround(v0);
        C[(cc + 1) * PV + ra] = tround(v1);
        C[cc * PV + ra + 8] = tround(v2);
        C[(cc + 1) * PV + ra + 8] = tround(v3);
      }
    }
  }
}

// E = exp(Q K^T / 8) -> swizzled E + per-tile row/col partials. 16 warps, 4x4.
__device__ __forceinline__ void gemm_s(
    const float* __restrict__ Q, const float* __restrict__ K, float* __restrict__ E,
    float* __restrict__ rowp, float* __restrict__ colp, int wid, int qr, int qc,
    int swm) {
  const int r0 = (wid & 3) * 32;
  const int c0 = (wid >> 2) * 32;
  float acc[2][4][4];
#pragma unroll
  for (int mi = 0; mi < 2; mi++)
#pragma unroll
    for (int nj = 0; nj < 4; nj++)
#pragma unroll
      for (int e = 0; e < 4; e++) acc[mi][nj][e] = 0.f;

#pragma unroll
  for (int k0 = 0; k0 < 64; k0 += 8) {
    uint32_t af[2][4];
#pragma unroll
    for (int mi = 0; mi < 2; mi++) {
      const float* ap = Q + (r0 + mi * 16 + qr) * PX + k0 + qc;
      af[mi][0] = fu(ap[0]);
      af[mi][1] = fu(ap[8 * PX]);
      af[mi][2] = fu(ap[4]);
      af[mi][3] = fu(ap[8 * PX + 4]);
    }
    uint32_t bf[4][2];
#pragma unroll
    for (int nj = 0; nj < 4; nj++) {
      const float* bp = K + (c0 + nj * 8 + qr) * PX + k0 + qc;
      bf[nj][0] = fu(bp[0]);
      bf[nj][1] = fu(bp[4]);
    }
#pragma unroll
    for (int mi = 0; mi < 2; mi++)
#pragma unroll
      for (int nj = 0; nj < 4; nj++)
        mma8(acc[mi][nj], af[mi][0], af[mi][1], af[mi][2], af[mi][3], bf[nj][0], bf[nj][1]);
  }

  float rs0[2] = {0.f, 0.f}, rs1[2] = {0.f, 0.f};
  float cs0[4] = {0.f, 0.f, 0.f, 0.f}, cs1[4] = {0.f, 0.f, 0.f, 0.f};
#pragma unroll
  for (int mi = 0; mi < 2; mi++) {
    const int ra = r0 + mi * 16 + qr;
#pragma unroll
    for (int nj = 0; nj < 4; nj++) {
      const int cc = c0 + nj * 8 + 2 * qc;
      const int cS = cc ^ swm;
      const float e0 = tround(__expf(0.125f * acc[mi][nj][0]));
      const float e1 = tround(__expf(0.125f * acc[mi][nj][1]));
      const float e2 = tround(__expf(0.125f * acc[mi][nj][2]));
      const float e3 = tround(__expf(0.125f * acc[mi][nj][3]));
      *(float2*)&E[ra * 128 + cS] = make_float2(e0, e1);
      *(float2*)&E[(ra + 8) * 128 + cS] = make_float2(e2, e3);
      rs0[mi] += e0 + e1;
      rs1[mi] += e2 + e3;
      cs0[nj] += e0 + e2;
      cs1[nj] += e1 + e3;
    }
  }
#pragma unroll
  for (int mi = 0; mi < 2; mi++) {
    rs0[mi] += __shfl_xor_sync(0xffffffffu, rs0[mi], 1);
    rs0[mi] += __shfl_xor_sync(0xffffffffu, rs0[mi], 2);
    rs1[mi] += __shfl_xor_sync(0xffffffffu, rs1[mi], 1);
    rs1[mi] += __shfl_xor_sync(0xffffffffu, rs1[mi], 2);
  }
  if (qc == 0) {
    float* rp = rowp + (wid >> 2) * 128;
#pragma unroll
    for (int mi = 0; mi < 2; mi++) {
      rp[r0 + mi * 16 + qr] = rs0[mi];
      rp[r0 + mi * 16 + qr + 8] = rs1[mi];
    }
  }
#pragma unroll
  for (int nj = 0; nj < 4; nj++) {
    cs0[nj] += __shfl_xor_sync(0xffffffffu, cs0[nj], 4);
    cs0[nj] += __shfl_xor_sync(0xffffffffu, cs0[nj], 8);
    cs0[nj] += __shfl_xor_sync(0xffffffffu, cs0[nj], 16);
    cs1[nj] += __shfl_xor_sync(0xffffffffu, cs1[nj], 4);
    cs1[nj] += __shfl_xor_sync(0xffffffffu, cs1[nj], 8);
    cs1[nj] += __shfl_xor_sync(0xffffffffu, cs1[nj], 16);
  }
  if (qr == 0) {
    float* cp = colp + (wid & 3) * 128;
#pragma unroll
    for (int nj = 0; nj < 4; nj++) {
      cp[c0 + nj * 8 + 2 * qc] = cs0[nj];
      cp[c0 + nj * 8 + 2 * qc + 1] = cs1[nj];
    }
  }
}

// out_l = x_l + rowsoftmax @ V2; direct GMEM RMW epilogue. 8 warps, 4(w)x2(c).
__device__ __forceinline__ void gemm_out_l(
    const float* __restrict__ E, const float* __restrict__ V2,
    const float* __restrict__ x_l, float* __restrict__ out_l, size_t planeoff,
    const float* __restrict__ invrow, int w8, int qr, int qc, int swm) {
  const int r0 = (w8 & 3) * 32;
  const int c0 = (w8 >> 2) * 32;
  float acc[2][4][4];
#pragma unroll
  for (int mi = 0; mi < 2; mi++)
#pragma unroll
    for (int nj = 0; nj < 4; nj++)
#pragma unroll
      for (int e = 0; e < 4; e++) acc[mi][nj][e] = 0.f;

#pragma unroll
  for (int k0 = 0; k0 < 128; k0 += 8) {
    const int col = (k0 + qc) ^ swm;
    uint32_t af[2][4];
#pragma unroll
    for (int mi = 0; mi < 2; mi++) {
      const int r = r0 + mi * 16 + qr;
      af[mi][0] = fu(E[r * 128 + col]);
      af[mi][1] = fu(E[(r + 8) * 128 + col]);
      af[mi][2] = fu(E[r * 128 + (col ^ 4)]);
      af[mi][3] = fu(E[(r + 8) * 128 + (col ^ 4)]);
    }
    uint32_t bf[4][2];
#pragma unroll
    for (int nj = 0; nj < 4; nj++) {
      const float* bp = V2 + (c0 + nj * 8 + qr) * PV + k0 + qc;
      bf[nj][0] = fu(bp[0]);
      bf[nj][1] = fu(bp[4]);
    }
#pragma unroll
    for (int mi = 0; mi < 2; mi++)
#pragma unroll
      for (int nj = 0; nj < 4; nj++)
        mma8(acc[mi][nj], af[mi][0], af[mi][1], af[mi][2], af[mi][3], bf[nj][0], bf[nj][1]);
  }

#pragma unroll
  for (int mi = 0; mi < 2; mi++) {
    const int ra = r0 + mi * 16 + qr;
    const float ir0 = invrow[ra], ir1 = invrow[ra + 8];
#pragma unroll
    for (int nj = 0; nj < 4; nj++) {
      const int cc = c0 + nj * 8 + 2 * qc;
      const float* xp = x_l + planeoff + (size_t)cc * PLANE;
      float* op = out_l + planeoff + (size_t)cc * PLANE;
      op[ra] = xp[ra] + acc[mi][nj][0] * ir0;
      op[PLANE + ra] = xp[PLANE + ra] + acc[mi][nj][1] * ir0;
      op[ra + 8] = xp[ra + 8] + acc[mi][nj][2] * ir1;
      op[PLANE + ra + 8] = xp[PLANE + ra + 8] + acc[mi][nj][3] * ir1;
    }
  }
}

// out_h = x_h + (colsoftmax)^T @ V1; V1^T @ E form. 8 warps, 2(c)x4(w). GMEM RMW.
__device__ __forceinline__ void gemm_out_h(
    const float* __restrict__ E, const float* __restrict__ V1,
    const float* __restrict__ x_h, float* __restrict__ out_h, size_t planeoff,
    const float* __restrict__ invcol, int w8, int qr, int qc) {
  const int r0 = (w8 & 1) * 32;   // c
  const int c0 = (w8 >> 1) * 32;  // w
  float acc[2][4][4];
#pragma unroll
  for (int mi = 0; mi < 2; mi++)
#pragma unroll
    for (int nj = 0; nj < 4; nj++)
#pragma unroll
      for (int e = 0; e < 4; e++) acc[mi][nj][e] = 0.f;

  const int sw1 = 8 * qc;
#pragma unroll
  for (int k0 = 0; k0 < 128; k0 += 8) {
    uint32_t af[2][4];
#pragma unroll
    for (int mi = 0; mi < 2; mi++) {
      const float* ap = V1 + (r0 + mi * 16 + qr) * PV + k0 + qc;
      af[mi][0] = fu(ap[0]);
      af[mi][1] = fu(ap[8 * PV]);
      af[mi][2] = fu(ap[4]);
      af[mi][3] = fu(ap[8 * PV + 4]);
    }
    const int rowA = (k0 + qc) * 128;
    const int rowB = (k0 + qc + 4) * 128;
    uint32_t bf[4][2];
#pragma unroll
    for (int nj = 0; nj < 4; nj++) {
      const int cc = c0 + nj * 8 + qr;
      bf[nj][0] = fu(E[rowA + (cc ^ sw1)]);
      bf[nj][1] = fu(E[rowB + (cc ^ sw1 ^ 4)]);
    }
#pragma unroll
    for (int mi = 0; mi < 2; mi++)
#pragma unroll
      for (int nj = 0; nj < 4; nj++)
        mma8(acc[mi][nj], af[mi][0], af[mi][1], af[mi][2], af[mi][3], bf[nj][0], bf[nj][1]);
  }

#pragma unroll
  for (int mi = 0; mi < 2; mi++) {
    const int ra = r0 + mi * 16 + qr;  // c
    const float* xp0 = x_h + planeoff + (size_t)ra * PLANE;
    const float* xp1 = x_h + planeoff + (size_t)(ra + 8) * PLANE;
    float* op0 = out_h + planeoff + (size_t)ra * PLANE;
    float* op1 = out_h + planeoff + (size_t)(ra + 8) * PLANE;
#pragma unroll
    for (int nj = 0; nj < 4; nj++) {
      const int w0 = c0 + nj * 8 + 2 * qc;
      const int w1 = w0 + 1;
      op0[w0] = xp0[w0] + acc[mi][nj][0] * invcol[w0];
      op0[w1] = xp0[w1] + acc[mi][nj][1] * invcol[w1];
      op1[w0] = xp1[w0] + acc[mi][nj][2] * invcol[w0];
      op1[w1] = xp1[w1] + acc[mi][nj][3] * invcol[w1];
    }
  }
}

__global__ __launch_bounds__(NTHR)
void scam_kernel(const float* __restrict__ x_l, const float* __restrict__ x_h,
                 const float* __restrict__ g1, const float* __restrict__ b1,
                 const float* __restrict__ g2, const float* __restrict__ b2,
                 const float* __restrict__ Wq, const float* __restrict__ Wk,
                 const float* __restrict__ Wv1, const float* __restrict__ Wv2,
                 float* __restrict__ out_l, float* __restrict__ out_h) {
  extern __shared__ float sm[];
  float* XA = sm + OFF_XA;
  float* XB = sm + OFF_XB;
  float* QB = sm + OFF_QB;
  float* KB = sm + OFF_KB;
  float* Ebuf = sm + OFF_E;
  uint32_t* WB1w = (uint32_t*)(sm + OFF_WB1);
  uint32_t* WB2w = (uint32_t*)(sm + OFF_WB2);
  uint16_t* WB1h = (uint16_t*)WB1w;
  uint16_t* WB2h = (uint16_t*)WB2w;
  float* rowp = sm + OFF_ROWP;
  float* colp = sm + OFF_COLP;
  float* meanl = sm + OFF_MEANL;
  float* rstdl = meanl + 128;
  float* meanh = rstdl + 128;
  float* rstdh = meanh + 128;
  float* t1q = sm + OFF_T;
  float* t2q = t1q + 64;
  float* t1k = t2q + 64;
  float* t2k = t1k + 64;
  float* invrow = sm + OFF_INV;
  float* invcol = invrow + 128;

  const int tid = threadIdx.x;
  const int lane = tid & 31;
  const int wid = tid >> 5;
  const int qr = lane >> 2;
  const int qc = lane & 3;
  const int swm = ((qr & 3) << 3) | (((qr >> 2) & 1) << 2);
  const int bh = blockIdx.x;
  const int b = bh >> 7;
  const int h = bh & 127;
  const size_t planeoff = ((size_t)b * kC * kH + (size_t)h) * kW;

  // ---- Phase 1: load x into swizzled c-major tiles ----
  for (int i = tid; i < kC * (kW / 4); i += NTHR) {
    const int c = i >> 5;
    const int w4 = ((i & 31) * 4) ^ ((c & 3) << 3);  // swizzle preserves 4-alignment
    const size_t goff = planeoff + (size_t)c * PLANE + (i & 31) * 4;
    *(float4*)(XA + c * 128 + w4) = *(const float4*)(x_l + goff);
    *(float4*)(XB + c * 128 + w4) = *(const float4*)(x_h + goff);
  }
  __syncthreads();

  // ---- Phase 2: LN stats (2 thr/row) + stage Wq/Wk (bf16 fold, warp halves) ----
  {
    const int rowid = tid >> 1;
    const int r = rowid & 127;
    const int half = tid & 1;
    const float* src = (rowid < 128 ? XA : XB);
    float s = 0.f, s2 = 0.f;
#pragma unroll
    for (int cu = 0; cu < 32; cu++) {
      const int c = half * 32 + cu;
      const float v = src[c * 128 + (r ^ ((c & 3) << 3))];
      s += v;
      s2 = fmaf(v, v, s2);
    }
    s += __shfl_xor_sync(0xffffffffu, s, 1);
    s2 += __shfl_xor_sync(0xffffffffu, s2, 1);
    if (half == 0) {
      const float m = s * (1.f / 64.f);
      const float var = fmaf(-m, m, s2 * (1.f / 64.f));
      const float rs = rsqrtf(var + 1e-5f);
      if (rowid < 128) { meanl[r] = m; rstdl[r] = rs; }
      else             { meanh[r] = m; rstdh[r] = rs; }
    }
  }
  if (tid < 256) stage_fold(Wq, g1, b1, WB1h, t1q, t2q, tid);
  else           stage_fold(Wk, g2, b2, WB2h, t1k, t2k, tid - 256);
  __syncthreads();

  // ---- Phase 3: Q (warps 0-7) || K (warps 8-15) ----
  if (wid < 8)
    gemm_xw<0>(XA, WB1w, QB, wid, qr, qc, meanl, rstdl, t1q, t2q);
  else
    gemm_xw<0>(XB, WB2w, KB, wid - 8, qr, qc, meanh, rstdh, t1k, t2k);
  __syncthreads();

  // ---- Phase 4: E = exp(QK^T/8) + partials (all 16 warps); stage Wv1/Wv2 ----
  gemm_s(QB, KB, Ebuf, rowp, colp, wid, qr, qc, swm);
  if (tid < 256) stage_raw(Wv1, WB1h, tid);
  else           stage_raw(Wv2, WB2h, tid - 256);
  __syncthreads();

  // ---- Phase 5: combine inverses; V1 (warps 0-7) || V2 (warps 8-15) ----
  if (tid < 128) {
    invrow[tid] = 1.f / (rowp[tid] + rowp[128 + tid] + rowp[256 + tid] + rowp[384 + tid]);
  } else if (tid < 256) {
    const int c = tid - 128;
    invcol[c] = 1.f / (colp[c] + colp[128 + c] + colp[256 + c] + colp[384 + c]);
  }
  if (wid < 8)
    gemm_xw<1>(XA, WB1w, QB, wid, qr, qc, nullptr, nullptr, nullptr, nullptr);
  else
    gemm_xw<1>(XB, WB2w, KB, wid - 8, qr, qc, nullptr, nullptr, nullptr, nullptr);
  __syncthreads();

  // ---- Phase 6: out_l (warps 0-7) || out_h (warps 8-15); GMEM RMW ----
  if (wid < 8)
    gemm_out_l(Ebuf, KB, x_l, out_l, planeoff, invrow, wid, qr, qc, swm);
  else
    gemm_out_h(Ebuf, QB, x_h, out_h, planeoff, invcol, wid - 8, qr, qc);
}

}  // namespace

extern "C" void kernel_launch(void* const* d_in, const int* in_sizes, int n_in,
                              void* d_out, int out_size) {
  const float* x_l = (const float*)d_in[0];
  const float* x_h = (const float*)d_in[1];
  const float* g1 = (const float*)d_in[2];
  const float* b1 = (const float*)d_in[3];
  const float* g2 = (const float*)d_in[4];
  const float* b2 = (const float*)d_in[5];
  const float* Wq = (const float*)d_in[6];
  const float* Wk = (const float*)d_in[7];
  const float* Wv1 = (const float*)d_in[8];
  const float* Wv2 = (const float*)d_in[9];

  float* out = (float*)d_out;
  float* out_l = out;
  float* out_h = out + (size_t)kB * kC * kH * kW;

  const size_t smem = (size_t)SMEM_FLOATS * sizeof(float);  // 227,328 B
  cudaFuncSetAttribute(scam_kernel, cudaFuncAttributeMaxDynamicSharedMemorySize, (int)smem);
  scam_kernel<<<kB * kH, NTHR, smem>>>(x_l, x_h, g1, b1, g2, b2, Wq, Wk, Wv1, Wv2,
                                       out_l, out_h);
}

// round 9
// speedup vs baseline: 1.1366x; 1.1366x over previous
#include <cuda_runtime.h>
#include <cstdint>

namespace {

constexpr int kB = 16, kC = 64, kH = 128, kW = 128;
constexpr int PX = 68;    // pitch, w-major [128 x 64] Q/K tiles; 68 % 32 == 4
constexpr int PV = 132;   // pitch, c-major [64 x 128] V tiles; 132 % 32 == 4
constexpr int PW = 136;   // pitch, c-major [64 x 128] x/out tiles; 136 % 32 == 8
constexpr int NTHR = 512;
constexpr int PLANE = kH * kW;
// E: 128x128, pitch 128, XOR-swizzled: word(r,c) = r*128 + (c ^ 8*(r&3) ^ 4*((r>>2)&1))
constexpr int SMEM_FLOATS =
    2 * 64 * PW + 2 * 128 * PX + 128 * 128 + 64 * PX + 2 * 512 + 4 * 128 + 4 * 64 + 2 * 128;

__device__ __forceinline__ uint32_t f2t(float x) {
  uint32_t r;
  asm("cvt.rna.tf32.f32 %0, %1;" : "=r"(r) : "f"(x));
  return r;
}
__device__ __forceinline__ float tround(float x) { return __uint_as_float(f2t(x)); }
__device__ __forceinline__ uint32_t fu(float x) { return __float_as_uint(x); }

__device__ __forceinline__ void mma8(float* c, uint32_t a0, uint32_t a1, uint32_t a2,
                                     uint32_t a3, uint32_t b0, uint32_t b1) {
  asm volatile(
      "mma.sync.aligned.m16n8k8.row.col.f32.tf32.tf32.f32 "
      "{%0,%1,%2,%3},{%4,%5,%6,%7},{%8,%9},{%0,%1,%2,%3};"
      : "+f"(c[0]), "+f"(c[1]), "+f"(c[2]), "+f"(c[3])
      : "r"(a0), "r"(a1), "r"(a2), "r"(a3), "r"(b0), "r"(b1));
}

// 64x64 weight fold, fp32, for a 256-thread half (t in [0,256)): 4 thr/row.
__device__ __forceinline__ void stage_fold256(
    const float* __restrict__ Wsrc, const float* __restrict__ g,
    const float* __restrict__ bb, float* __restrict__ WB,
    float* __restrict__ t1, float* __restrict__ t2, int t) {
  const int j = t >> 2;
  const int c0 = (t & 3) * 16;
  float s1 = 0.f, s2 = 0.f;
#pragma unroll
  for (int u = 0; u < 16; u++) {
    const int c = c0 + u;
    const float raw = Wsrc[j * 64 + c];
    const float wf = tround(raw * g[c]);
    WB[j * PX + c] = wf;
    s1 += wf;
    s2 += raw * bb[c];
  }
  s1 += __shfl_xor_sync(0xffffffffu, s1, 1);
  s1 += __shfl_xor_sync(0xffffffffu, s1, 2);
  s2 += __shfl_xor_sync(0xffffffffu, s2, 1);
  s2 += __shfl_xor_sync(0xffffffffu, s2, 2);
  if ((t & 3) == 0) { t1[j] = s1; t2[j] = s2; }
}

// raw weight stage, all 512 threads: 8 thr/row.
__device__ __forceinline__ void stage_raw512(
    const float* __restrict__ Wsrc, float* __restrict__ WB, int tid) {
  const int j = tid >> 3;
  const int c0 = (tid & 7) * 8;
#pragma unroll
  for (int u = 0; u < 8; u++) WB[j * PX + c0 + u] = tround(Wsrc[j * 64 + c0 + u]);
}

// 8-warp xw gemm (R7-proven): grid 4(m)x2(n), 32x32 tiles. C = A @ WB^T.
// A c-major [c][PW]. MODE 0: LN epilogue -> w-major [w][PX]. MODE 1: -> c-major [c][PV].
template <int MODE>
__device__ __forceinline__ void gemm_xw8(
    const float* __restrict__ A, const float* __restrict__ WB, float* __restrict__ C,
    int w8, int qr, int qc, const float* __restrict__ mean,
    const float* __restrict__ rstd, const float* __restrict__ t1,
    const float* __restrict__ t2) {
  const int r0 = (w8 & 3) * 32;
  const int c0 = (w8 >> 2) * 32;
  float acc[2][4][4];
#pragma unroll
  for (int mi = 0; mi < 2; mi++)
#pragma unroll
    for (int nj = 0; nj < 4; nj++)
#pragma unroll
      for (int e = 0; e < 4; e++) acc[mi][nj][e] = 0.f;

#pragma unroll
  for (int k0 = 0; k0 < 64; k0 += 8) {
    uint32_t af[2][4];
#pragma unroll
    for (int mi = 0; mi < 2; mi++) {
      const float* ap = A + (k0 + qc) * PW + r0 + mi * 16 + qr;
      af[mi][0] = f2t(ap[0]);
      af[mi][1] = f2t(ap[8]);
      af[mi][2] = f2t(ap[4 * PW]);
      af[mi][3] = f2t(ap[4 * PW + 8]);
    }
    uint32_t bf[4][2];
#pragma unroll
    for (int nj = 0; nj < 4; nj++) {
      const float* bp = WB + (c0 + nj * 8 + qr) * PX + k0 + qc;
      bf[nj][0] = fu(bp[0]);
      bf[nj][1] = fu(bp[4]);
    }
#pragma unroll
    for (int mi = 0; mi < 2; mi++)
#pragma unroll
      for (int nj = 0; nj < 4; nj++)
        mma8(acc[mi][nj], af[mi][0], af[mi][1], af[mi][2], af[mi][3], bf[nj][0], bf[nj][1]);
  }

#pragma unroll
  for (int mi = 0; mi < 2; mi++) {
    const int ra = r0 + mi * 16 + qr;
#pragma unroll
    for (int nj = 0; nj < 4; nj++) {
      const int cc = c0 + nj * 8 + 2 * qc;
      float v0 = acc[mi][nj][0], v1 = acc[mi][nj][1];
      float v2 = acc[mi][nj][2], v3 = acc[mi][nj][3];
      if (MODE == 0) {
        const float m0 = mean[ra], rs0 = rstd[ra];
        const float m1 = mean[ra + 8], rs1 = rstd[ra + 8];
        const float ta = t1[cc], tb = t1[cc + 1];
        const float ua = t2[cc], ub = t2[cc + 1];
        v0 = rs0 * (v0 - m0 * ta) + ua;
        v1 = rs0 * (v1 - m0 * tb) + ub;
        v2 = rs1 * (v2 - m1 * ta) + ua;
        v3 = rs1 * (v3 - m1 * tb) + ub;
        *(float2*)&C[ra * PX + cc] = make_float2(tround(v0), tround(v1));
        *(float2*)&C[(ra + 8) * PX + cc] = make_float2(tround(v2), tround(v3));
      } else {
        C[cc * PV + ra] = tround(v0);
        C[(cc + 1) * PV + ra] = tround(v1);
        C[cc * PV + ra + 8] = tround(v2);
        C[(cc + 1) * PV + ra + 8] = tround(v3);
      }
    }
  }
}

// 16-warp xw gemm (R6-proven): grid 4x4, 32x16 tiles. MODE 1 only (V gemms).
__device__ __forceinline__ void gemm_xw16_v(
    const float* __restrict__ A, const float* __restrict__ WB, float* __restrict__ C,
    int wid, int qr, int qc) {
  const int r0 = (wid & 3) * 32;
  const int c0 = (wid >> 2) * 16;
  float acc[2][2][4];
#pragma unroll
  for (int mi = 0; mi < 2; mi++)
#pragma unroll
    for (int nj = 0; nj < 2; nj++)
#pragma unroll
      for (int e = 0; e < 4; e++) acc[mi][nj][e] = 0.f;

#pragma unroll
  for (int k0 = 0; k0 < 64; k0 += 8) {
    uint32_t af[2][4];
#pragma unroll
    for (int mi = 0; mi < 2; mi++) {
      const float* ap = A + (k0 + qc) * PW + r0 + mi * 16 + qr;
      af[mi][0] = f2t(ap[0]);
      af[mi][1] = f2t(ap[8]);
      af[mi][2] = f2t(ap[4 * PW]);
      af[mi][3] = f2t(ap[4 * PW + 8]);
    }
    uint32_t bf[2][2];
#pragma unroll
    for (int nj = 0; nj < 2; nj++) {
      const float* bp = WB + (c0 + nj * 8 + qr) * PX + k0 + qc;
      bf[nj][0] = fu(bp[0]);
      bf[nj][1] = fu(bp[4]);
    }
#pragma unroll
    for (int mi = 0; mi < 2; mi++)
#pragma unroll
      for (int nj = 0; nj < 2; nj++)
        mma8(acc[mi][nj], af[mi][0], af[mi][1], af[mi][2], af[mi][3], bf[nj][0], bf[nj][1]);
  }

#pragma unroll
  for (int mi = 0; mi < 2; mi++) {
    const int ra = r0 + mi * 16 + qr;
#pragma unroll
    for (int nj = 0; nj < 2; nj++) {
      const int cc = c0 + nj * 8 + 2 * qc;
      C[cc * PV + ra] = tround(acc[mi][nj][0]);
      C[(cc + 1) * PV + ra] = tround(acc[mi][nj][1]);
      C[cc * PV + ra + 8] = tround(acc[mi][nj][2]);
      C[(cc + 1) * PV + ra + 8] = tround(acc[mi][nj][3]);
    }
  }
}

// E = exp(Q K^T / 8) -> swizzled E + per-tile row/col partials. 16 warps, 4x4.
__device__ __forceinline__ void gemm_s(
    const float* __restrict__ Q, const float* __restrict__ K, float* __restrict__ E,
    float* __restrict__ rowp, float* __restrict__ colp, int wid, int qr, int qc,
    int swm) {
  const int r0 = (wid & 3) * 32;
  const int c0 = (wid >> 2) * 32;
  float acc[2][4][4];
#pragma unroll
  for (int mi = 0; mi < 2; mi++)
#pragma unroll
    for (int nj = 0; nj < 4; nj++)
#pragma unroll
      for (int e = 0; e < 4; e++) acc[mi][nj][e] = 0.f;

#pragma unroll
  for (int k0 = 0; k0 < 64; k0 += 8) {
    uint32_t af[2][4];
#pragma unroll
    for (int mi = 0; mi < 2; mi++) {
      const float* ap = Q + (r0 + mi * 16 + qr) * PX + k0 + qc;
      af[mi][0] = fu(ap[0]);
      af[mi][1] = fu(ap[8 * PX]);
      af[mi][2] = fu(ap[4]);
      af[mi][3] = fu(ap[8 * PX + 4]);
    }
    uint32_t bf[4][2];
#pragma unroll
    for (int nj = 0; nj < 4; nj++) {
      const float* bp = K + (c0 + nj * 8 + qr) * PX + k0 + qc;
      bf[nj][0] = fu(bp[0]);
      bf[nj][1] = fu(bp[4]);
    }
#pragma unroll
    for (int mi = 0; mi < 2; mi++)
#pragma unroll
      for (int nj = 0; nj < 4; nj++)
        mma8(acc[mi][nj], af[mi][0], af[mi][1], af[mi][2], af[mi][3], bf[nj][0], bf[nj][1]);
  }

  float rs0[2] = {0.f, 0.f}, rs1[2] = {0.f, 0.f};
  float cs0[4] = {0.f, 0.f, 0.f, 0.f}, cs1[4] = {0.f, 0.f, 0.f, 0.f};
#pragma unroll
  for (int mi = 0; mi < 2; mi++) {
    const int ra = r0 + mi * 16 + qr;
#pragma unroll
    for (int nj = 0; nj < 4; nj++) {
      const int cc = c0 + nj * 8 + 2 * qc;
      const int cS = cc ^ swm;
      const float e0 = tround(__expf(0.125f * acc[mi][nj][0]));
      const float e1 = tround(__expf(0.125f * acc[mi][nj][1]));
      const float e2 = tround(__expf(0.125f * acc[mi][nj][2]));
      const float e3 = tround(__expf(0.125f * acc[mi][nj][3]));
      *(float2*)&E[ra * 128 + cS] = make_float2(e0, e1);
      *(float2*)&E[(ra + 8) * 128 + cS] = make_float2(e2, e3);
      rs0[mi] += e0 + e1;
      rs1[mi] += e2 + e3;
      cs0[nj] += e0 + e2;
      cs1[nj] += e1 + e3;
    }
  }
#pragma unroll
  for (int mi = 0; mi < 2; mi++) {
    rs0[mi] += __shfl_xor_sync(0xffffffffu, rs0[mi], 1);
    rs0[mi] += __shfl_xor_sync(0xffffffffu, rs0[mi], 2);
    rs1[mi] += __shfl_xor_sync(0xffffffffu, rs1[mi], 1);
    rs1[mi] += __shfl_xor_sync(0xffffffffu, rs1[mi], 2);
  }
  if (qc == 0) {
    float* rp = rowp + (wid >> 2) * 128;
#pragma unroll
    for (int mi = 0; mi < 2; mi++) {
      rp[r0 + mi * 16 + qr] = rs0[mi];
      rp[r0 + mi * 16 + qr + 8] = rs1[mi];
    }
  }
#pragma unroll
  for (int nj = 0; nj < 4; nj++) {
    cs0[nj] += __shfl_xor_sync(0xffffffffu, cs0[nj], 4);
    cs0[nj] += __shfl_xor_sync(0xffffffffu, cs0[nj], 8);
    cs0[nj] += __shfl_xor_sync(0xffffffffu, cs0[nj], 16);
    cs1[nj] += __shfl_xor_sync(0xffffffffu, cs1[nj], 4);
    cs1[nj] += __shfl_xor_sync(0xffffffffu, cs1[nj], 8);
    cs1[nj] += __shfl_xor_sync(0xffffffffu, cs1[nj], 16);
  }
  if (qr == 0) {
    float* cp = colp + (wid & 3) * 128;
#pragma unroll
    for (int nj = 0; nj < 4; nj++) {
      cp[c0 + nj * 8 + 2 * qc] = cs0[nj];
      cp[c0 + nj * 8 + 2 * qc + 1] = cs1[nj];
    }
  }
}

// 8-warp (R7-proven): XL[c][w] += invrow[w] * (E @ V2)[w][c]. 4(w)x2(c), K=128.
__device__ __forceinline__ void gemm_out_l(
    const float* __restrict__ E, const float* __restrict__ V2, float* __restrict__ XL,
    const float* __restrict__ invrow, int w8, int qr, int qc, int swm) {
  const int r0 = (w8 & 3) * 32;
  const int c0 = (w8 >> 2) * 32;
  float acc[2][4][4];
#pragma unroll
  for (int mi = 0; mi < 2; mi++)
#pragma unroll
    for (int nj = 0; nj < 4; nj++)
#pragma unroll
      for (int e = 0; e < 4; e++) acc[mi][nj][e] = 0.f;

#pragma unroll
  for (int k0 = 0; k0 < 128; k0 += 8) {
    const int col = (k0 + qc) ^ swm;
    uint32_t af[2][4];
#pragma unroll
    for (int mi = 0; mi < 2; mi++) {
      const int r = r0 + mi * 16 + qr;
      af[mi][0] = fu(E[r * 128 + col]);
      af[mi][1] = fu(E[(r + 8) * 128 + col]);
      af[mi][2] = fu(E[r * 128 + (col ^ 4)]);
      af[mi][3] = fu(E[(r + 8) * 128 + (col ^ 4)]);
    }
    uint32_t bf[4][2];
#pragma unroll
    for (int nj = 0; nj < 4; nj++) {
      const float* bp = V2 + (c0 + nj * 8 + qr) * PV + k0 + qc;
      bf[nj][0] = fu(bp[0]);
      bf[nj][1] = fu(bp[4]);
    }
#pragma unroll
    for (int mi = 0; mi < 2; mi++)
#pragma unroll
      for (int nj = 0; nj < 4; nj++)
        mma8(acc[mi][nj], af[mi][0], af[mi][1], af[mi][2], af[mi][3], bf[nj][0], bf[nj][1]);
  }

#pragma unroll
  for (int mi = 0; mi < 2; mi++) {
    const int ra = r0 + mi * 16 + qr;
    const float ir0 = invrow[ra], ir1 = invrow[ra + 8];
#pragma unroll
    for (int nj = 0; nj < 4; nj++) {
      const int cc = c0 + nj * 8 + 2 * qc;
      XL[cc * PW + ra] += acc[mi][nj][0] * ir0;
      XL[(cc + 1) * PW + ra] += acc[mi][nj][1] * ir0;
      XL[cc * PW + ra + 8] += acc[mi][nj][2] * ir1;
      XL[(cc + 1) * PW + ra + 8] += acc[mi][nj][3] * ir1;
    }
  }
}

// 8-warp (R7-proven): out_h^T = V1^T @ E. 2(c)x4(w) grid, 32x32 tiles.
__device__ __forceinline__ void gemm_out_h(
    const float* __restrict__ E, const float* __restrict__ V1, float* __restrict__ XH,
    const float* __restrict__ invcol, int w8, int qr, int qc) {
  const int r0 = (w8 & 1) * 32;   // c dimension (64)
  const int c0 = (w8 >> 1) * 32;  // w dimension (128)
  float acc[2][4][4];
#pragma unroll
  for (int mi = 0; mi < 2; mi++)
#pragma unroll
    for (int nj = 0; nj < 4; nj++)
#pragma unroll
      for (int e = 0; e < 4; e++) acc[mi][nj][e] = 0.f;

  const int sw1 = 8 * qc;
#pragma unroll
  for (int k0 = 0; k0 < 128; k0 += 8) {
    uint32_t af[2][4];
#pragma unroll
    for (int mi = 0; mi < 2; mi++) {
      const float* ap = V1 + (r0 + mi * 16 + qr) * PV + k0 + qc;
      af[mi][0] = fu(ap[0]);
      af[mi][1] = fu(ap[8 * PV]);
      af[mi][2] = fu(ap[4]);
      af[mi][3] = fu(ap[8 * PV + 4]);
    }
    const int rowA = (k0 + qc) * 128;
    const int rowB = (k0 + qc + 4) * 128;
    uint32_t bf[4][2];
#pragma unroll
    for (int nj = 0; nj < 4; nj++) {
      const int cc = c0 + nj * 8 + qr;
      bf[nj][0] = fu(E[rowA + (cc ^ sw1)]);
      bf[nj][1] = fu(E[rowB + (cc ^ sw1 ^ 4)]);
    }
#pragma unroll
    for (int mi = 0; mi < 2; mi++)
#pragma unroll
      for (int nj = 0; nj < 4; nj++)
        mma8(acc[mi][nj], af[mi][0], af[mi][1], af[mi][2], af[mi][3], bf[nj][0], bf[nj][1]);
  }

#pragma unroll
  for (int mi = 0; mi < 2; mi++) {
    const int ra = r0 + mi * 16 + qr;  // c
#pragma unroll
    for (int nj = 0; nj < 4; nj++) {
      const int w0 = c0 + nj * 8 + 2 * qc;
      const int w1 = w0 + 1;
      XH[ra * PW + w0] += acc[mi][nj][0] * invcol[w0];
      XH[ra * PW + w1] += acc[mi][nj][1] * invcol[w1];
      XH[(ra + 8) * PW + w0] += acc[mi][nj][2] * invcol[w0];
      XH[(ra + 8) * PW + w1] += acc[mi][nj][3] * invcol[w1];
    }
  }
}

__global__ __launch_bounds__(NTHR)
void scam_kernel(const float* __restrict__ x_l, const float* __restrict__ x_h,
                 const float* __restrict__ g1, const float* __restrict__ b1,
                 const float* __restrict__ g2, const float* __restrict__ b2,
                 const float* __restrict__ Wq, const float* __restrict__ Wk,
                 const float* __restrict__ Wv1, const float* __restrict__ Wv2,
                 float* __restrict__ out_l, float* __restrict__ out_h) {
  extern __shared__ float sm[];
  float* XL = sm;                    // [64][PW] c-major fp32 residual + out stage
  float* XH = XL + 64 * PW;
  float* QV1 = XH + 64 * PW;         // Q w-major [128][PX], then V1 c-major [64][PV]
  float* KV2 = QV1 + 128 * PX;       // K, then V2
  float* Ebuf = KV2 + 128 * PX;      // [128][128] swizzled exp(attn)
  float* WB1 = Ebuf + 128 * 128;     // [64][PX] weight buffer 1
  float* WB2 = Ebuf;                 // weight buffer 2 ALIASES E (dead until gemm_s)
  float* rowp = WB1 + 64 * PX;       // [4][128]... layout below
  float* colp = rowp + 2 * 128;      // (R6 offsets kept: rowp 2*128 slot + colp 4*128)
  float* meanl = colp + 4 * 128;
  float* rstdl = meanl + 128;
  float* meanh = rstdl + 128;
  float* rstdh = meanh + 128;
  float* t1q = rstdh + 128;
  float* t2q = t1q + 64;
  float* t1k = t2q + 64;
  float* t2k = t1k + 64;
  float* invrow = t2k + 64;
  float* invcol = invrow + 128;
  // NOTE: gemm_s writes rowp[0..511]; rowp slot is 2*128 but colp follows -> rowp
  // needs 4*128. Give rowp the combined 2*128+... -> use dedicated arrays:
  // (offsets sized in SMEM_FLOATS: 2*512 for rowp+colp)
  rowp = WB1 + 64 * PX;          // [4][128] = 512
  colp = rowp + 512;             // [4][128] = 512
  meanl = colp + 512;
  rstdl = meanl + 128;
  meanh = rstdl + 128;
  rstdh = meanh + 128;
  t1q = rstdh + 128;
  t2q = t1q + 64;
  t1k = t2q + 64;
  t2k = t1k + 64;
  invrow = t2k + 64;
  invcol = invrow + 128;

  const int tid = threadIdx.x;
  const int lane = tid & 31;
  const int wid = tid >> 5;
  const int qr = lane >> 2;
  const int qc = lane & 3;
  const int swm = ((qr & 3) << 3) | (((qr >> 2) & 1) << 2);
  const int bh = blockIdx.x;
  const int b = bh >> 7;
  const int h = bh & 127;
  const size_t planeoff = ((size_t)b * kC * kH + (size_t)h) * kW;

  // ---- P1: load x slices, c-major float4 STS (conflict-free, coalesced) ----
  for (int i = tid; i < kC * (kW / 4); i += NTHR) {
    const int c = i >> 5;
    const int w4 = (i & 31) * 4;
    const size_t goff = planeoff + (size_t)c * PLANE + w4;
    *(float4*)(XL + c * PW + w4) = *(const float4*)(x_l + goff);
    *(float4*)(XH + c * PW + w4) = *(const float4*)(x_h + goff);
  }
  __syncthreads();

  // ---- P2: LN stats (2 thr/row) + stage Wq->WB1 and Wk->WB2 in halves ----
  {
    const int rowid = tid >> 1;
    const int r = rowid & 127;
    const int half = tid & 1;
    const float* src = (rowid < 128 ? XL : XH) + half * 32 * PW + r;
    float s = 0.f, s2 = 0.f;
#pragma unroll
    for (int c = 0; c < 32; c++) {
      const float v = src[c * PW];
      s += v;
      s2 = fmaf(v, v, s2);
    }
    s += __shfl_xor_sync(0xffffffffu, s, 1);
    s2 += __shfl_xor_sync(0xffffffffu, s2, 1);
    if (half == 0) {
      const float m = s * (1.f / 64.f);
      const float var = fmaf(-m, m, s2 * (1.f / 64.f));
      const float rs = rsqrtf(var + 1e-5f);
      if (rowid < 128) { meanl[r] = m; rstdl[r] = rs; }
      else             { meanh[r] = m; rstdh[r] = rs; }
    }
  }
  if (tid < 256) stage_fold256(Wq, g1, b1, WB1, t1q, t2q, tid);
  else           stage_fold256(Wk, g2, b2, WB2, t1k, t2k, tid - 256);
  __syncthreads();

  // ---- P3: Q (warps 0-7) || K (warps 8-15) ----
  if (wid < 8)
    gemm_xw8<0>(XL, WB1, QV1, wid, qr, qc, meanl, rstdl, t1q, t2q);
  else
    gemm_xw8<0>(XH, WB2, KV2, wid - 8, qr, qc, meanh, rstdh, t1k, t2k);
  __syncthreads();

  // ---- P4: E = exp(QK^T/8) (writes over WB2 region too) + stage Wv1->WB1 ----
  gemm_s(QV1, KV2, Ebuf, rowp, colp, wid, qr, qc, swm);
  stage_raw512(Wv1, WB1, tid);
  __syncthreads();

  // ---- P5: combine inverses; V1 = XL @ Wv1^T (16 warps, overwrites Q) ----
  if (tid < 128) {
    invrow[tid] = 1.f / (rowp[tid] + rowp[128 + tid] + rowp[256 + tid] + rowp[384 + tid]);
  } else if (tid < 256) {
    const int c = tid - 128;
    invcol[c] = 1.f / (colp[c] + colp[128 + c] + colp[256 + c] + colp[384 + c]);
  }
  gemm_xw16_v(XL, WB1, QV1, wid, qr, qc);
  __syncthreads();

  stage_raw512(Wv2, WB1, tid);
  __syncthreads();

  gemm_xw16_v(XH, WB1, KV2, wid, qr, qc);
  __syncthreads();

  // ---- P6: out_l (warps 0-7) || out_h (warps 8-15), smem epilogues ----
  if (wid < 8)
    gemm_out_l(Ebuf, KV2, XL, invrow, wid, qr, qc, swm);
  else
    gemm_out_h(Ebuf, QV1, XH, invcol, wid - 8, qr, qc);
  __syncthreads();

  // ---- writeout: conflict-free LDS.128, coalesced STG ----
  for (int i = tid; i < kC * (kW / 4); i += NTHR) {
    const int c = i >> 5;
    const int w4 = (i & 31) * 4;
    const size_t goff = planeoff + (size_t)c * PLANE + w4;
    *(float4*)(out_l + goff) = *(const float4*)(XL + c * PW + w4);
    *(float4*)(out_h + goff) = *(const float4*)(XH + c * PW + w4);
  }
}

}  // namespace

extern "C" void kernel_launch(void* const* d_in, const int* in_sizes, int n_in,
                              void* d_out, int out_size) {
  const float* x_l = (const float*)d_in[0];
  const float* x_h = (const float*)d_in[1];
  const float* g1 = (const float*)d_in[2];
  const float* b1 = (const float*)d_in[3];
  const float* g2 = (const float*)d_in[4];
  const float* b2 = (const float*)d_in[5];
  const float* Wq = (const float*)d_in[6];
  const float* Wk = (const float*)d_in[7];
  const float* Wv1 = (const float*)d_in[8];
  const float* Wv2 = (const float*)d_in[9];

  float* out = (float*)d_out;
  float* out_l = out;
  float* out_h = out + (size_t)kB * kC * kH * kW;

  const size_t smem = (size_t)SMEM_FLOATS * sizeof(float);  // ~225 KB
  cudaFuncSetAttribute(scam_kernel, cudaFuncAttributeMaxDynamicSharedMemorySize, (int)smem);
  scam_kernel<<<kB * kH, NTHR, smem>>>(x_l, x_h, g1, b1, g2, b2, Wq, Wk, Wv1, Wv2,
                                       out_l, out_h);
}